// round 2
// baseline (speedup 1.0000x reference)
#include <cuda_runtime.h>
#include <cstdint>

#define NN 100000
#define EE 1600000
#define FULLMASK 0xffffffffu

// Scratch (no allocations allowed): projection planes [4][N][64] (q,k,v,skip),
// per-edge scores [E][4], CSR row pointers.
__device__ float g_proj[(size_t)4 * NN * 64];     // 102.4 MB
__device__ float g_scores[(size_t)EE * 4];        // 25.6 MB
__device__ int   g_rowptr[NN + 1];

// ---------------------------------------------------------------------------
// K0: row_ptr[n] = lower_bound(edge_dst, n). edge_dst is sorted.
// ---------------------------------------------------------------------------
__global__ void rowptr_kernel(const int* __restrict__ edst) {
    int n = blockIdx.x * blockDim.x + threadIdx.x;
    if (n > NN) return;
    int lo = 0, hi = EE;
    while (lo < hi) {
        int mid = (lo + hi) >> 1;
        if (edst[mid] < n) lo = mid + 1; else hi = mid;
    }
    g_rowptr[n] = lo;
}

// ---------------------------------------------------------------------------
// K1: fused projection GEMM.  proj[p][n][c] = feat[n] @ W_p[:,c] + b_p[c]
// 256 threads: thread j -> plane p = j>>6, col = j&63.  Column of W cached in
// registers (64 regs), feat tiles (8 rows) staged in smem, 256 rows/block.
// ---------------------------------------------------------------------------
__global__ void __launch_bounds__(256, 2) proj_kernel(
    const float* __restrict__ feat,
    const float* __restrict__ Wq, const float* __restrict__ bq,
    const float* __restrict__ Wk, const float* __restrict__ bk,
    const float* __restrict__ Wv, const float* __restrict__ bv,
    const float* __restrict__ Ws, const float* __restrict__ bs)
{
    __shared__ float fs[8][64];
    const int tid = threadIdx.x;
    const int p = tid >> 6, col = tid & 63;
    const float* W = (p == 0) ? Wq : (p == 1) ? Wk : (p == 2) ? Wv : Ws;
    const float* B = (p == 0) ? bq : (p == 1) ? bk : (p == 2) ? bv : bs;

    float w[64];
#pragma unroll
    for (int k = 0; k < 64; k++) w[k] = W[k * 64 + col];
    const float bias = B[col];
    float* out = g_proj + (size_t)p * NN * 64;

    const int row0 = blockIdx.x * 256;
    for (int it = 0; it < 32; it++) {
        const int rbase = row0 + it * 8;
        if (rbase >= NN) break;
        __syncthreads();
        for (int idx = tid; idx < 512; idx += 256) {
            int r = rbase + (idx >> 6);
            fs[idx >> 6][idx & 63] = (r < NN) ? feat[(size_t)r * 64 + (idx & 63)] : 0.f;
        }
        __syncthreads();
        float acc[8];
#pragma unroll
        for (int r = 0; r < 8; r++) acc[r] = bias;
#pragma unroll
        for (int k = 0; k < 64; k++) {
            const float wv = w[k];
#pragma unroll
            for (int r = 0; r < 8; r++) acc[r] += wv * fs[r][k];
        }
#pragma unroll
        for (int r = 0; r < 8; r++) {
            int row = rbase + r;
            if (row < NN) out[(size_t)row * 64 + col] = acc[r];
        }
    }
}

// ---------------------------------------------------------------------------
// K2: per-(edge,head) attention logits.
// scores[e][h] = dot16(q[src[e]][h], k[dst[e]][h]) / sqrt(16)
// ---------------------------------------------------------------------------
__global__ void scores_kernel(const int* __restrict__ esrc,
                              const int* __restrict__ edst)
{
    const int tid = blockIdx.x * blockDim.x + threadIdx.x;
    if (tid >= EE * 4) return;
    const int e = tid >> 2, h = tid & 3;
    const int s = esrc[e], d = edst[e];
    const float4* q = (const float4*)(g_proj + (size_t)s * 64 + h * 16);
    const float4* k = (const float4*)(g_proj + (size_t)NN * 64 + (size_t)d * 64 + h * 16);
    float acc = 0.f;
#pragma unroll
    for (int i = 0; i < 4; i++) {
        float4 a = q[i], b = k[i];
        acc += a.x * b.x + a.y * b.y + a.z * b.z + a.w * b.w;
    }
    g_scores[tid] = acc * 0.25f;
}

// ---------------------------------------------------------------------------
// K3: one warp per destination node.
// Pass 1: online softmax stats (m, s) per head over the node's edge range.
// Pass 2: agg[d] = sum_e softmax_w(e,h(d)) * v[src[e]][d]   (lane owns d=lane
//         and d=lane+32; coalesced 128B v loads, broadcast score loads)
// Epilogue: gated skip, LayerNorm, PReLU.
// ---------------------------------------------------------------------------
__global__ void agg_kernel(const int* __restrict__ esrc,
                           const float* __restrict__ Wg, const float* __restrict__ bg,
                           const float* __restrict__ ln_g, const float* __restrict__ ln_b,
                           const float* __restrict__ prelu_a,
                           float* __restrict__ out)
{
    const int warp = (blockIdx.x * blockDim.x + threadIdx.x) >> 5;
    const int lane = threadIdx.x & 31;
    if (warp >= NN) return;
    const int node = warp;
    const int beg = g_rowptr[node], end = g_rowptr[node + 1];

    // ---- pass 1: per-head online (max, sumexp) ----
    float m[4], s[4];
#pragma unroll
    for (int h = 0; h < 4; h++) { m[h] = -3e38f; s[h] = 0.f; }
    for (int e = beg + lane; e < end; e += 32) {
        float4 sc = *(const float4*)(g_scores + (size_t)e * 4);
        float scv[4] = {sc.x, sc.y, sc.z, sc.w};
#pragma unroll
        for (int h = 0; h < 4; h++) {
            float nm = fmaxf(m[h], scv[h]);
            s[h] = s[h] * __expf(m[h] - nm) + __expf(scv[h] - nm);
            m[h] = nm;
        }
    }
#pragma unroll
    for (int off = 16; off; off >>= 1) {
#pragma unroll
        for (int h = 0; h < 4; h++) {
            float om = __shfl_xor_sync(FULLMASK, m[h], off);
            float os = __shfl_xor_sync(FULLMASK, s[h], off);
            float nm = fmaxf(m[h], om);
            s[h] = s[h] * __expf(m[h] - nm) + os * __expf(om - nm);
            m[h] = nm;
        }
    }
    float inv[4];
#pragma unroll
    for (int h = 0; h < 4; h++) inv[h] = (s[h] > 0.f) ? 1.f / s[h] : 0.f;

    // lane owns dims d0 = lane (heads 0/1) and d1 = lane+32 (heads 2/3)
    const bool lowh = (lane < 16);
    const float mA = lowh ? m[0] : m[1], iA = lowh ? inv[0] : inv[1];
    const float mB = lowh ? m[2] : m[3], iB = lowh ? inv[2] : inv[3];

    const float* vplane = g_proj + (size_t)2 * NN * 64;
    float acc0 = 0.f, acc1 = 0.f;
    for (int e = beg; e < end; e++) {
        float4 sc = *(const float4*)(g_scores + (size_t)e * 4);  // broadcast
        const int src = esrc[e];                                  // broadcast
        const float* vr = vplane + (size_t)src * 64;
        const float sA = lowh ? sc.x : sc.y;
        const float sB = lowh ? sc.z : sc.w;
        const float w0 = __expf(sA - mA) * iA;
        const float w1 = __expf(sB - mB) * iB;
        acc0 += w0 * vr[lane];
        acc1 += w1 * vr[lane + 32];
    }

    // ---- gated skip ----
    const float* splane = g_proj + (size_t)3 * NN * 64;
    const float sk0 = splane[(size_t)node * 64 + lane];
    const float sk1 = splane[(size_t)node * 64 + lane + 32];
    float gp = sk0 * Wg[lane]      + acc0 * Wg[64 + lane] + (sk0 - acc0) * Wg[128 + lane]
             + sk1 * Wg[lane + 32] + acc1 * Wg[96 + lane] + (sk1 - acc1) * Wg[160 + lane];
#pragma unroll
    for (int off = 16; off; off >>= 1) gp += __shfl_xor_sync(FULLMASK, gp, off);
    const float gate = 1.f / (1.f + __expf(-(gp + bg[0])));
    const float r0 = gate * sk0 + (1.f - gate) * acc0;
    const float r1 = gate * sk1 + (1.f - gate) * acc1;

    // ---- LayerNorm over 64 dims ----
    float sum = r0 + r1, sq = r0 * r0 + r1 * r1;
#pragma unroll
    for (int off = 16; off; off >>= 1) {
        sum += __shfl_xor_sync(FULLMASK, sum, off);
        sq  += __shfl_xor_sync(FULLMASK, sq,  off);
    }
    const float mu = sum * (1.f / 64.f);
    const float var = sq * (1.f / 64.f) - mu * mu;
    const float rstd = rsqrtf(var + 1e-5f);
    const float a = prelu_a[0];

    float o0 = (r0 - mu) * rstd * ln_g[lane]      + ln_b[lane];
    float o1 = (r1 - mu) * rstd * ln_g[lane + 32] + ln_b[lane + 32];
    o0 = (o0 >= 0.f) ? o0 : a * o0;
    o1 = (o1 >= 0.f) ? o1 : a * o1;
    out[(size_t)node * 64 + lane]      = o0;
    out[(size_t)node * 64 + lane + 32] = o1;
}

// ---------------------------------------------------------------------------
extern "C" void kernel_launch(void* const* d_in, const int* in_sizes, int n_in,
                              void* d_out, int out_size)
{
    const float* feat    = (const float*)d_in[0];
    const int*   esrc    = (const int*)  d_in[1];
    const int*   edst    = (const int*)  d_in[2];
    const float* Wq      = (const float*)d_in[3];
    const float* bq      = (const float*)d_in[4];
    const float* Wk      = (const float*)d_in[5];
    const float* bk      = (const float*)d_in[6];
    const float* Wv      = (const float*)d_in[7];
    const float* bv      = (const float*)d_in[8];
    const float* Ws      = (const float*)d_in[9];
    const float* bs      = (const float*)d_in[10];
    const float* Wg      = (const float*)d_in[11];
    const float* bg      = (const float*)d_in[12];
    const float* ln_g    = (const float*)d_in[13];
    const float* ln_b    = (const float*)d_in[14];
    const float* prelu_a = (const float*)d_in[15];
    float* out = (float*)d_out;

    rowptr_kernel<<<(NN + 1 + 255) / 256, 256>>>(edst);
    proj_kernel<<<(NN + 255) / 256, 256>>>(feat, Wq, bq, Wk, bk, Wv, bv, Ws, bs);
    scores_kernel<<<(EE * 4 + 255) / 256, 256>>>(esrc, edst);
    agg_kernel<<<(NN * 32 + 255) / 256, 256>>>(esrc, Wg, bg, ln_g, ln_b, prelu_a, out);
}